// round 11
// baseline (speedup 1.0000x reference)
#include <cuda_runtime.h>
#include <math.h>

// Problem constants
#define S_N   256
#define V_N   200
#define F_N   5
#define G_N   80
#define NT    16
#define NR    5
#define NROT  16
#define EPSF  1e-5f

#define TWO_PI_F 6.28318530717958647692f
#define DTH_F    0.39269908169872415481f
#define LOG2E_F  1.44269504088896340736f

typedef unsigned long long ull;

// Scratch
__device__ float d_GDN[(size_t)S_N * NROT * G_N * 8];   // [s][r][g=p*16+k][8]
__device__ float d_PMAX[(size_t)2 * S_N * 400];         // [half][s][f*80+gp]

// ---------------- packed f32x2 helpers ----------------
__device__ __forceinline__ ull ffma2(ull a, ull b, ull c) {
    ull d;
    asm("fma.rn.f32x2 %0, %1, %2, %3;" : "=l"(d) : "l"(a), "l"(b), "l"(c));
    return d;
}
__device__ __forceinline__ ull addf2(ull a, ull b) {
    ull d;
    asm("add.rn.f32x2 %0, %1, %2;" : "=l"(d) : "l"(a), "l"(b));
    return d;
}
__device__ __forceinline__ ull pack2(float x) {
    ull d;
    asm("mov.b64 %0, {%1, %1};" : "=l"(d) : "f"(x));
    return d;
}
__device__ __forceinline__ float2 unpack2(ull v) {
    float2 f;
    asm("mov.b64 {%0, %1}, %2;" : "=f"(f.x), "=f"(f.y) : "l"(v));
    return f;
}
__device__ __forceinline__ float ex2f(float x) {
    float r;
    asm("ex2.approx.f32 %0, %1;" : "=f"(r) : "f"(x));
    return r;
}

// theta-gaussian weight, packed to f32x2
__device__ __forceinline__ ull mk_tg(float tv, float rdel, float sL,
                                     float c0, float c1) {
    float tr = tv + rdel;
    float c  = (tr >= TWO_PI_F) ? c1 : c0;
    float x  = fmaf(tr, sL, c);
    return pack2(ex2f(-x * x));
}

// Normalize 5 (den,f0..f4) pair-groups and write one GDN row.
__device__ __forceinline__ void gdn_epilogue(const ull* acc, float* gbase)
{
#pragma unroll
    for (int p = 0; p < NR; p++) {
        float2 q0 = unpack2(acc[p * 3 + 0]);
        float2 q1 = unpack2(acc[p * 3 + 1]);
        float2 q2 = unpack2(acc[p * 3 + 2]);
        float inv = 1.0f / (q0.x + EPSF);
        float4 o0 = make_float4(q0.y * inv, q1.x * inv, q1.y * inv, q2.x * inv);
        float4 o1 = make_float4(q2.y * inv, 0.0f, 0.0f, 0.0f);
        float4* po = (float4*)(gbase + (size_t)p * 128);
        po[0] = o0;
        po[1] = o1;
    }
}

// ---------------------------------------------------------------------------
// k12: one block per s, 256 threads = (v-half 0/1) x (r2 0..7, k 0..15).
// Each thread accumulates TWO rotations (r2, r2+8) over its half's 100 v.
// Software-pipelined: tg for v+1 computed during v's FMA burst; ALL 8 row
// loads (next first-half + current second-half) issued before the burst.
// ---------------------------------------------------------------------------
__global__ __launch_bounds__(256)
void k12(const float* __restrict__ feat,
         const float* __restrict__ rho,
         const float* __restrict__ theta,
         const float* __restrict__ mask,
         const float* __restrict__ mu_rho,
         const float* __restrict__ sigma_rho,
         const float* __restrict__ mu_theta,
         const float* __restrict__ sigma_theta)
{
    __shared__ float As[(V_N + 2) * 32];   // +2 zero pad rows for prefetch overrun
    __shared__ float t_s[V_N + 4];         // +4 pad for pipelined theta read

    int s   = blockIdx.x;
    int tid = threadIdx.x;
    int vh  = tid >> 7;                    // v half
    int l   = tid & 127;
    int r2  = l >> 4;                      // 0..7
    int k   = l & 15;

    // theta-gaussian constants (one k, two rotations)
    float mu_k  = __ldg(&mu_theta[k]);
    float st    = __ldg(&sigma_theta[k]);
    float sL    = sqrtf(LOG2E_F / (st * st + EPSF));
    float rdelA = (float)r2 * DTH_F;
    float rdelB = (float)(r2 + 8) * DTH_F;
    float c0    = -mu_k * sL;
    float c1    = -(TWO_PI_F + mu_k) * sL;

    // ---- stage A, all 200 rows (float4 stores) ----
    if (tid < V_N) {
        int v   = tid;
        int idx = s * V_N + v;
        float rhv = rho[idx];
        float m   = mask[idx];
        t_s[v]    = theta[idx];
        float fv[5];
#pragma unroll
        for (int f = 0; f < 5; f++) fv[f] = feat[idx * 5 + f];
        float ar[32];
#pragma unroll
        for (int p = 0; p < NR; p++) {
            float mr = __ldg(&mu_rho[p * 16]);
            float sr = __ldg(&sigma_rho[p * 16]);
            float d  = rhv - mr;
            float rg = ex2f(-(d * d) * (LOG2E_F / (sr * sr + EPSF)));
            float rm = rg * m;
            ar[p * 6] = rm;
#pragma unroll
            for (int f = 0; f < 5; f++) ar[p * 6 + 1 + f] = rm * fv[f];
        }
        ar[30] = 0.0f; ar[31] = 0.0f;
        float4* dst = (float4*)(As + v * 32);
#pragma unroll
        for (int j4 = 0; j4 < 8; j4++) dst[j4] = ((const float4*)ar)[j4];
    } else if (tid < V_N + 16) {
        ((float4*)(As + V_N * 32))[tid - V_N] = make_float4(0.f, 0.f, 0.f, 0.f);
        if (tid < V_N + 4) t_s[V_N + (tid - V_N)] = 0.0f;
    }
    __syncthreads();

    // ---- main loop: 100 v of this half, 2 rotations per thread ----
    ull accA[16], accB[16];
#pragma unroll
    for (int j = 0; j < 16; j++) { accA[j] = 0ull; accB[j] = 0ull; }

    const int vbase = vh * 100;
    ulonglong2 qA[4], qB[4];
    {
        const ulonglong2* row0 = (const ulonglong2*)(As + vbase * 32);
#pragma unroll
        for (int j = 0; j < 4; j++) qA[j] = row0[j];
    }
    // initial tg (for v = vbase)
    float tv0 = t_s[vbase];
    ull tgA = mk_tg(tv0, rdelA, sL, c0, c1);
    ull tgB = mk_tg(tv0, rdelB, sL, c0, c1);

    // One pipelined step: consumes CUR + tgA/tgB for row VV, prefetches
    // row VV+1 first half into NXT, loads row VV second half, and computes
    // tg for VV+1 between the two FMA bursts.
#define K12_STEP(VV, CUR, NXT)                                                \
    {                                                                         \
        const ulonglong2* rn = (const ulonglong2*)(As + ((VV) + 1) * 32);     \
        _Pragma("unroll")                                                     \
        for (int j = 0; j < 4; j++) NXT[j] = rn[j];                           \
        ulonglong2 rv[4];                                                     \
        const ulonglong2* rp = (const ulonglong2*)(As + (VV) * 32) + 4;       \
        _Pragma("unroll")                                                     \
        for (int j = 0; j < 4; j++) rv[j] = rp[j];                            \
        float tvn = t_s[(VV) + 1];                                            \
        ull tA = tgA, tB = tgB;                                               \
        _Pragma("unroll")                                                     \
        for (int j = 0; j < 4; j++) {                                         \
            accA[2 * j + 0] = ffma2(tA, CUR[j].x, accA[2 * j + 0]);           \
            accA[2 * j + 1] = ffma2(tA, CUR[j].y, accA[2 * j + 1]);           \
            accB[2 * j + 0] = ffma2(tB, CUR[j].x, accB[2 * j + 0]);           \
            accB[2 * j + 1] = ffma2(tB, CUR[j].y, accB[2 * j + 1]);           \
        }                                                                     \
        tgA = mk_tg(tvn, rdelA, sL, c0, c1);                                  \
        tgB = mk_tg(tvn, rdelB, sL, c0, c1);                                  \
        _Pragma("unroll")                                                     \
        for (int j = 0; j < 4; j++) {                                         \
            accA[8 + 2 * j + 0] = ffma2(tA, rv[j].x, accA[8 + 2 * j + 0]);    \
            accA[8 + 2 * j + 1] = ffma2(tA, rv[j].y, accA[8 + 2 * j + 1]);    \
            accB[8 + 2 * j + 0] = ffma2(tB, rv[j].x, accB[8 + 2 * j + 0]);    \
            accB[8 + 2 * j + 1] = ffma2(tB, rv[j].y, accB[8 + 2 * j + 1]);    \
        }                                                                     \
    }

#pragma unroll 2
    for (int vo = 0; vo < 100; vo += 2) {
        int v = vbase + vo;
        K12_STEP(v,     qA, qB)
        K12_STEP(v + 1, qB, qA)
    }
#undef K12_STEP

    // ---- combine halves via smem, two 16 KB phases (reuse As) ----
    ull* cbuf = (ull*)As;   // 16 * 128 ull = 16 KB
    __syncthreads();        // done reading As/t_s
    if (vh == 1) {
#pragma unroll
        for (int j = 0; j < 16; j++) cbuf[j * 128 + l] = accA[j];
    }
    __syncthreads();
    if (vh == 0) {
#pragma unroll
        for (int j = 0; j < 16; j++) accA[j] = addf2(accA[j], cbuf[j * 128 + l]);
        gdn_epilogue(accA, d_GDN + (((size_t)s * NROT + r2) * G_N + k) * 8);
    }
    __syncthreads();
    if (vh == 1) {
#pragma unroll
        for (int j = 0; j < 16; j++) cbuf[j * 128 + l] = accB[j];
    }
    __syncthreads();
    if (vh == 0) {
#pragma unroll
        for (int j = 0; j < 16; j++) accB[j] = addf2(accB[j], cbuf[j * 128 + l]);
        gdn_epilogue(accB, d_GDN + (((size_t)s * NROT + r2 + 8) * G_N + k) * 8);
    }
}

// ---------------------------------------------------------------------------
// k3: grid (S_N, 2) = (s, rotation-half of 8). 320 threads = (rg 0..3, gp);
// each rg handles 2 rotations sharing every W load; FFMA2 accumulation
// (pairs (f0,f1),(f2,f3),(f4,pad)). Writes per-half rot-max to d_PMAX.
// ---------------------------------------------------------------------------
__global__ __launch_bounds__(320) void k3_conv(const float* __restrict__ Wc)
{
    __shared__ float Wsh[G_N * G_N];    // 25.6 KB
    __shared__ float gsh[8 * G_N * 8];  // 20.5 KB (reused for reduction)

    int s    = blockIdx.x;
    int half = blockIdx.y;
    int tid  = threadIdx.x;
    int rg   = tid / 80;
    int gp   = tid % 80;

    {
        const float4* wsrc = (const float4*)Wc;
        float4* wdst = (float4*)Wsh;
        for (int i = tid; i < G_N * G_N / 4; i += 320) wdst[i] = wsrc[i];
        const float4* src = (const float4*)(d_GDN + ((size_t)s * 16 + half * 8) * 640);
        float4* dst = (float4*)gsh;
        for (int i = tid; i < 1280; i += 320) dst[i] = src[i];
    }
    __syncthreads();

    const float* ga = &gsh[(rg * 2) * 640];
    const float* gb = ga + 640;
    ull aA0 = 0, aA1 = 0, aA2 = 0, aB0 = 0, aB1 = 0, aB2 = 0;
#pragma unroll 4
    for (int g = 0; g < G_N; g++) {
        ull w2 = pack2(Wsh[g * 80 + gp]);
        ulonglong2 qa = *(const ulonglong2*)&ga[g * 8];   // (f0,f1),(f2,f3)
        ull qa2 = *(const ull*)&ga[g * 8 + 4];            // (f4, pad0)
        ulonglong2 qb = *(const ulonglong2*)&gb[g * 8];
        ull qb2 = *(const ull*)&gb[g * 8 + 4];
        aA0 = ffma2(w2, qa.x, aA0); aA1 = ffma2(w2, qa.y, aA1); aA2 = ffma2(w2, qa2, aA2);
        aB0 = ffma2(w2, qb.x, aB0); aB1 = ffma2(w2, qb.y, aB1); aB2 = ffma2(w2, qb2, aB2);
    }
    float2 a01 = unpack2(aA0), a23 = unpack2(aA1), a4 = unpack2(aA2);
    float2 b01 = unpack2(aB0), b23 = unpack2(aB1), b4 = unpack2(aB2);
    float m0 = fmaxf(a01.x, b01.x), m1 = fmaxf(a01.y, b01.y);
    float m2 = fmaxf(a23.x, b23.x), m3 = fmaxf(a23.y, b23.y);
    float m4 = fmaxf(a4.x,  b4.x);

    __syncthreads();
    float* red = gsh;
    red[rg * 400 + 0 * 80 + gp] = m0;
    red[rg * 400 + 1 * 80 + gp] = m1;
    red[rg * 400 + 2 * 80 + gp] = m2;
    red[rg * 400 + 3 * 80 + gp] = m3;
    red[rg * 400 + 4 * 80 + gp] = m4;
    __syncthreads();

    float* pout = d_PMAX + (size_t)half * S_N * 400 + (size_t)s * 400;
    {
        int j = tid;
        float v = fmaxf(fmaxf(red[j], red[400 + j]), fmaxf(red[800 + j], red[1200 + j]));
        pout[j] = v;
        if (tid < 80) {
            int j2 = 320 + tid;
            float v2 = fmaxf(fmaxf(red[j2], red[400 + j2]),
                             fmaxf(red[800 + j2], red[1200 + j2]));
            pout[j2] = v2;
        }
    }
}

// ---------------------------------------------------------------------------
// k4: grid 64, block 320 = (s_local 0..3, g 0..79). fw staged via smem chunks.
// ---------------------------------------------------------------------------
__global__ __launch_bounds__(320) void k4_fcc(const float* __restrict__ bc,
                                              const float* __restrict__ fw,
                                              const float* __restrict__ fb,
                                              float* __restrict__ out)
{
    __shared__ float fwsh[100 * 80];   // 32 KB chunk
    __shared__ float dsh[4 * 400];

    int tid = threadIdx.x;
    int sl  = tid / 80;
    int g   = tid % 80;
    int sb  = blockIdx.x * 4;

    for (int i = tid; i < 4 * 400; i += 320) {
        int s_loc = i / 400, j = i % 400;
        int s = sb + s_loc;
        float v = fmaxf(d_PMAX[(size_t)s * 400 + j],
                        d_PMAX[(size_t)S_N * 400 + (size_t)s * 400 + j]);
        dsh[i] = fmaxf(v + bc[j], 0.0f);
    }

    float acc = 0.0f;
#pragma unroll
    for (int c = 0; c < 4; c++) {
        __syncthreads();
        const float4* src = (const float4*)(fw + (size_t)c * 100 * 80);
        float4* dst = (float4*)fwsh;
        for (int i = tid; i < 2000; i += 320) dst[i] = src[i];
        __syncthreads();

        const float* dr = &dsh[sl * 400 + c * 100];
#pragma unroll 5
        for (int j = 0; j < 100; j++)
            acc = fmaf(dr[j], fwsh[j * 80 + g], acc);
    }

    out[(size_t)(sb + sl) * 80 + g] = fb[g] + acc;
}

// ---------------------------------------------------------------------------
// k5: distances + score + loss. 1024 threads; warp-per-pair, float4 loads,
// shfl reductions. out: [0:20480) desc, [20480] loss, [20481:20609) score
// ---------------------------------------------------------------------------
__global__ __launch_bounds__(1024) void k5_loss(float* __restrict__ out)
{
    __shared__ float sdist[128];
    __shared__ float stats[4];

    int tid  = threadIdx.x;
    int w    = tid >> 5;
    int lane = tid & 31;
    const float* gd = out;

#pragma unroll
    for (int i = 0; i < 4; i++) {
        int p  = w + 32 * i;     // 0..127
        int il = p & 63;
        const float *xa, *xb;
        if (p < 64) { xa = gd + (size_t)(64 + il) * 80;  xb = gd + (size_t)il * 80; }
        else        { xa = gd + (size_t)(128 + il) * 80; xb = gd + (size_t)(192 + il) * 80; }
        float sum = 0.0f;
        if (lane < 20) {
            float4 a4 = ((const float4*)xa)[lane];
            float4 b4 = ((const float4*)xb)[lane];
            float dx = a4.x - b4.x, dy = a4.y - b4.y;
            float dz = a4.z - b4.z, dw = a4.w - b4.w;
            sum = dx * dx + dy * dy + dz * dz + dw * dw;
        }
#pragma unroll
        for (int off = 16; off; off >>= 1)
            sum += __shfl_xor_sync(0xffffffffu, sum, off);
        if (lane == 0) { sdist[p] = sum; out[20481 + p] = sum; }
    }
    __syncthreads();

    if (w == 0) {
        float v1 = fmaxf(sdist[lane], 0.0f);
        float v2 = fmaxf(sdist[lane + 32], 0.0f);
        float sum = v1 + v2;
#pragma unroll
        for (int off = 16; off; off >>= 1)
            sum += __shfl_xor_sync(0xffffffffu, sum, off);
        float m = sum * (1.0f / 64.0f);
        float q = (v1 - m) * (v1 - m) + (v2 - m) * (v2 - m);
#pragma unroll
        for (int off = 16; off; off >>= 1)
            q += __shfl_xor_sync(0xffffffffu, q, off);
        if (lane == 0) { stats[0] = m; stats[1] = q; }
    } else if (w == 1) {
        float v1 = fmaxf(10.0f - sdist[64 + lane], 0.0f);
        float v2 = fmaxf(10.0f - sdist[96 + lane], 0.0f);
        float sum = v1 + v2;
#pragma unroll
        for (int off = 16; off; off >>= 1)
            sum += __shfl_xor_sync(0xffffffffu, sum, off);
        float m = sum * (1.0f / 64.0f);
        float q = (v1 - m) * (v1 - m) + (v2 - m) * (v2 - m);
#pragma unroll
        for (int off = 16; off; off >>= 1)
            q += __shfl_xor_sync(0xffffffffu, q, off);
        if (lane == 0) { stats[2] = m; stats[3] = q; }
    }
    __syncthreads();

    if (tid == 0)
        out[20480] = sqrtf(stats[1] / 63.0f) + sqrtf(stats[3] / 63.0f)
                   + stats[0] + stats[2];
}

// ---------------------------------------------------------------------------
extern "C" void kernel_launch(void* const* d_in, const int* in_sizes, int n_in,
                              void* d_out, int out_size)
{
    const float* input_feat  = (const float*)d_in[0];
    const float* rho_coords  = (const float*)d_in[1];
    const float* theta_coord = (const float*)d_in[2];
    const float* mask        = (const float*)d_in[3];
    const float* mu_rho      = (const float*)d_in[4];
    const float* sigma_rho   = (const float*)d_in[5];
    const float* mu_theta    = (const float*)d_in[6];
    const float* sigma_theta = (const float*)d_in[7];
    const float* W_conv      = (const float*)d_in[8];
    const float* b_conv      = (const float*)d_in[9];
    const float* fcc_w       = (const float*)d_in[10];
    const float* fcc_b       = (const float*)d_in[11];
    float* out = (float*)d_out;

    k12<<<S_N, 256>>>(input_feat, rho_coords, theta_coord, mask,
                      mu_rho, sigma_rho, mu_theta, sigma_theta);
    k3_conv<<<dim3(S_N, 2), 320>>>(W_conv);
    k4_fcc<<<S_N / 4, 320>>>(b_conv, fcc_w, fcc_b, out);
    k5_loss<<<1, 1024>>>(out);
}

// round 12
// speedup vs baseline: 1.0780x; 1.0780x over previous
#include <cuda_runtime.h>
#include <math.h>

// Problem constants
#define S_N   256
#define V_N   200
#define F_N   5
#define G_N   80
#define NT    16
#define NR    5
#define NROT  16
#define EPSF  1e-5f

#define TWO_PI_F 6.28318530717958647692f
#define DTH_F    0.39269908169872415481f
#define LOG2E_F  1.44269504088896340736f

typedef unsigned long long ull;

// Scratch
// d_GDN layout: [s][g][f][rp][2] floats, rp in 0..7, pair = (r=rp, r=rp+8)
// per s: 80*5*8*2 = 6400 floats (3200 ull)
__device__ float d_GDN[(size_t)S_N * 6400];
__device__ float d_DESC[(size_t)S_N * 400];    // [s][f*80+gp], post max+bias+relu

// ---------------- packed f32x2 helpers ----------------
__device__ __forceinline__ ull ffma2(ull a, ull b, ull c) {
    ull d;
    asm("fma.rn.f32x2 %0, %1, %2, %3;" : "=l"(d) : "l"(a), "l"(b), "l"(c));
    return d;
}
__device__ __forceinline__ ull addf2(ull a, ull b) {
    ull d;
    asm("add.rn.f32x2 %0, %1, %2;" : "=l"(d) : "l"(a), "l"(b));
    return d;
}
__device__ __forceinline__ ull pack2(float x) {
    ull d;
    asm("mov.b64 %0, {%1, %1};" : "=l"(d) : "f"(x));
    return d;
}
__device__ __forceinline__ ull pack2f(float a, float b) {
    ull d;
    asm("mov.b64 %0, {%1, %2};" : "=l"(d) : "f"(a), "f"(b));
    return d;
}
__device__ __forceinline__ float2 unpack2(ull v) {
    float2 f;
    asm("mov.b64 {%0, %1}, %2;" : "=f"(f.x), "=f"(f.y) : "l"(v));
    return f;
}
__device__ __forceinline__ float ex2f(float x) {
    float r;
    asm("ex2.approx.f32 %0, %1;" : "=f"(r) : "f"(x));
    return r;
}

// ---------------------------------------------------------------------------
// k12: one block per s, 256 threads = (v-half 0/1) x (r2 0..7, k 0..15).
// Each thread accumulates TWO rotations (r2, r2+8) over its half's 100 v,
// sharing every A-row load across both rotations. Ping-pong LDS.128 prefetch;
// halves combined via smem in 2 phases. Epilogue writes the [g][f][rp][2]
// layout that k3 consumes.
// ---------------------------------------------------------------------------
__global__ __launch_bounds__(256, 2)
void k12(const float* __restrict__ feat,
         const float* __restrict__ rho,
         const float* __restrict__ theta,
         const float* __restrict__ mask,
         const float* __restrict__ mu_rho,
         const float* __restrict__ sigma_rho,
         const float* __restrict__ mu_theta,
         const float* __restrict__ sigma_theta)
{
    __shared__ float As[(V_N + 2) * 32];   // +2 zero pad rows for prefetch overrun
    __shared__ float t_s[V_N];

    int s   = blockIdx.x;
    int tid = threadIdx.x;
    int vh  = tid >> 7;                    // v half
    int l   = tid & 127;
    int r2  = l >> 4;                      // 0..7
    int k   = l & 15;

    // theta-gaussian constants (one k, two rotations)
    float mu_k  = __ldg(&mu_theta[k]);
    float st    = __ldg(&sigma_theta[k]);
    float sL    = sqrtf(LOG2E_F / (st * st + EPSF));
    float rdelA = (float)r2 * DTH_F;
    float rdelB = (float)(r2 + 8) * DTH_F;
    float c0    = -mu_k * sL;
    float c1    = -(TWO_PI_F + mu_k) * sL;

    // ---- stage A, all 200 rows (float4 stores) ----
    if (tid < V_N) {
        int v   = tid;
        int idx = s * V_N + v;
        float rhv = rho[idx];
        float m   = mask[idx];
        t_s[v]    = theta[idx];
        float fv[5];
#pragma unroll
        for (int f = 0; f < 5; f++) fv[f] = feat[idx * 5 + f];
        float ar[32];
#pragma unroll
        for (int p = 0; p < NR; p++) {
            float mr = __ldg(&mu_rho[p * 16]);
            float sr = __ldg(&sigma_rho[p * 16]);
            float d  = rhv - mr;
            float rg = ex2f(-(d * d) * (LOG2E_F / (sr * sr + EPSF)));
            float rm = rg * m;
            ar[p * 6] = rm;
#pragma unroll
            for (int f = 0; f < 5; f++) ar[p * 6 + 1 + f] = rm * fv[f];
        }
        ar[30] = 0.0f; ar[31] = 0.0f;
        float4* dst = (float4*)(As + v * 32);
#pragma unroll
        for (int j4 = 0; j4 < 8; j4++) dst[j4] = ((const float4*)ar)[j4];
    } else if (tid < V_N + 16) {
        ((float4*)(As + V_N * 32))[tid - V_N] = make_float4(0.f, 0.f, 0.f, 0.f);
    }
    __syncthreads();

    // ---- main loop: 100 v of this half, 2 rotations per thread ----
    ull accA[16], accB[16];
#pragma unroll
    for (int j = 0; j < 16; j++) { accA[j] = 0ull; accB[j] = 0ull; }

    const int vbase = vh * 100;
    ulonglong2 qA[4], qB[4];
    {
        const ulonglong2* row0 = (const ulonglong2*)(As + vbase * 32);
#pragma unroll
        for (int j = 0; j < 4; j++) qA[j] = row0[j];
    }

#pragma unroll 2
    for (int vo = 0; vo < 100; vo += 2) {
        int v = vbase + vo;
        // --- even: consume qA, prefetch row v+1 into qB ---
        {
            const ulonglong2* rn = (const ulonglong2*)(As + (v + 1) * 32);
#pragma unroll
            for (int j = 0; j < 4; j++) qB[j] = rn[j];
        }
        {
            float tv  = t_s[v];
            float trA = tv + rdelA;
            float cA  = (trA >= TWO_PI_F) ? c1 : c0;
            float xA  = fmaf(trA, sL, cA);
            ull tgA   = pack2(ex2f(-xA * xA));
            float trB = tv + rdelB;
            float cB  = (trB >= TWO_PI_F) ? c1 : c0;
            float xB  = fmaf(trB, sL, cB);
            ull tgB   = pack2(ex2f(-xB * xB));
#pragma unroll
            for (int j = 0; j < 4; j++) {
                accA[2 * j + 0] = ffma2(tgA, qA[j].x, accA[2 * j + 0]);
                accA[2 * j + 1] = ffma2(tgA, qA[j].y, accA[2 * j + 1]);
                accB[2 * j + 0] = ffma2(tgB, qA[j].x, accB[2 * j + 0]);
                accB[2 * j + 1] = ffma2(tgB, qA[j].y, accB[2 * j + 1]);
            }
            const ulonglong2* rv = (const ulonglong2*)(As + v * 32) + 4;
#pragma unroll
            for (int j = 0; j < 4; j++) {
                ulonglong2 q = rv[j];
                accA[8 + 2 * j + 0] = ffma2(tgA, q.x, accA[8 + 2 * j + 0]);
                accA[8 + 2 * j + 1] = ffma2(tgA, q.y, accA[8 + 2 * j + 1]);
                accB[8 + 2 * j + 0] = ffma2(tgB, q.x, accB[8 + 2 * j + 0]);
                accB[8 + 2 * j + 1] = ffma2(tgB, q.y, accB[8 + 2 * j + 1]);
            }
        }
        // --- odd: consume qB, prefetch row v+2 into qA ---
        {
            const ulonglong2* rn = (const ulonglong2*)(As + (v + 2) * 32);
#pragma unroll
            for (int j = 0; j < 4; j++) qA[j] = rn[j];
        }
        {
            float tv  = t_s[v + 1];
            float trA = tv + rdelA;
            float cA  = (trA >= TWO_PI_F) ? c1 : c0;
            float xA  = fmaf(trA, sL, cA);
            ull tgA   = pack2(ex2f(-xA * xA));
            float trB = tv + rdelB;
            float cB  = (trB >= TWO_PI_F) ? c1 : c0;
            float xB  = fmaf(trB, sL, cB);
            ull tgB   = pack2(ex2f(-xB * xB));
#pragma unroll
            for (int j = 0; j < 4; j++) {
                accA[2 * j + 0] = ffma2(tgA, qB[j].x, accA[2 * j + 0]);
                accA[2 * j + 1] = ffma2(tgA, qB[j].y, accA[2 * j + 1]);
                accB[2 * j + 0] = ffma2(tgB, qB[j].x, accB[2 * j + 0]);
                accB[2 * j + 1] = ffma2(tgB, qB[j].y, accB[2 * j + 1]);
            }
            const ulonglong2* rv = (const ulonglong2*)(As + (v + 1) * 32) + 4;
#pragma unroll
            for (int j = 0; j < 4; j++) {
                ulonglong2 q = rv[j];
                accA[8 + 2 * j + 0] = ffma2(tgA, q.x, accA[8 + 2 * j + 0]);
                accA[8 + 2 * j + 1] = ffma2(tgA, q.y, accA[8 + 2 * j + 1]);
                accB[8 + 2 * j + 0] = ffma2(tgB, q.x, accB[8 + 2 * j + 0]);
                accB[8 + 2 * j + 1] = ffma2(tgB, q.y, accB[8 + 2 * j + 1]);
            }
        }
    }

    // ---- combine halves via smem, two 16 KB phases (reuse As) ----
    ull* cbuf = (ull*)As;   // 16 * 128 ull = 16 KB
    __syncthreads();        // done reading As/t_s
    if (vh == 1) {
#pragma unroll
        for (int j = 0; j < 16; j++) cbuf[j * 128 + l] = accA[j];
    }
    __syncthreads();
    if (vh == 0) {
#pragma unroll
        for (int j = 0; j < 16; j++) accA[j] = addf2(accA[j], cbuf[j * 128 + l]);
    }
    __syncthreads();
    if (vh == 1) {
#pragma unroll
        for (int j = 0; j < 16; j++) cbuf[j * 128 + l] = accB[j];
    }
    __syncthreads();
    if (vh == 0) {
#pragma unroll
        for (int j = 0; j < 16; j++) accB[j] = addf2(accB[j], cbuf[j * 128 + l]);

        // ---- normalize + write GDN [s][g][f][rp][2] ----
        // acc pair layout: p*3+0=(den,f0), p*3+1=(f1,f2), p*3+2=(f3,f4)
        ull* gdn = (ull*)d_GDN + (size_t)s * 3200;   // [g][f][rp] in ull units
#pragma unroll
        for (int p = 0; p < NR; p++) {
            float2 a0 = unpack2(accA[p * 3 + 0]);
            float2 a1 = unpack2(accA[p * 3 + 1]);
            float2 a2 = unpack2(accA[p * 3 + 2]);
            float2 b0 = unpack2(accB[p * 3 + 0]);
            float2 b1 = unpack2(accB[p * 3 + 1]);
            float2 b2 = unpack2(accB[p * 3 + 2]);
            float invA = 1.0f / (a0.x + EPSF);
            float invB = 1.0f / (b0.x + EPSF);
            int g = p * 16 + k;
            ull* gb = gdn + ((size_t)g * 5) * 8 + r2;
            gb[0 * 8] = pack2f(a0.y * invA, b0.y * invB);   // f0
            gb[1 * 8] = pack2f(a1.x * invA, b1.x * invB);   // f1
            gb[2 * 8] = pack2f(a1.y * invA, b1.y * invB);   // f2
            gb[3 * 8] = pack2f(a2.x * invA, b2.x * invB);   // f3
            gb[4 * 8] = pack2f(a2.y * invA, b2.y * invB);   // f4
        }
    }
}

// ---------------------------------------------------------------------------
// k3: one block per s, 400 threads = (f 0..4, gp 0..79). Per g: 1 W-LDS +
// 4 broadcast LDS.128 feed ALL 16 rotations (8 FFMA2 on (r2,r2+8) pairs).
// Max over rotations in registers, then bias + relu -> d_DESC.
// ---------------------------------------------------------------------------
__global__ __launch_bounds__(400) void k3_conv(const float* __restrict__ Wc,
                                               const float* __restrict__ bc)
{
    __shared__ float Wsh[G_N * G_N];    // 25.6 KB
    __shared__ ull   gdsh[3200];        // 25.6 KB, [g][f][rp]

    int s   = blockIdx.x;
    int tid = threadIdx.x;
    int f   = tid / 80;
    int gp  = tid % 80;

    {
        const float4* wsrc = (const float4*)Wc;
        float4* wdst = (float4*)Wsh;
        for (int i = tid; i < 1600; i += 400) wdst[i] = wsrc[i];
        const float4* gsrc = (const float4*)(d_GDN + (size_t)s * 6400);
        float4* gdst = (float4*)gdsh;
        for (int i = tid; i < 1600; i += 400) gdst[i] = gsrc[i];
    }
    __syncthreads();

    ull acc[8];
#pragma unroll
    for (int j = 0; j < 8; j++) acc[j] = 0ull;

#pragma unroll 4
    for (int g = 0; g < G_N; g++) {
        ull w2 = pack2(Wsh[g * 80 + gp]);
        const ulonglong2* rp = (const ulonglong2*)(gdsh + ((size_t)g * 5 + f) * 8);
        ulonglong2 q0 = rp[0], q1 = rp[1], q2 = rp[2], q3 = rp[3];
        acc[0] = ffma2(w2, q0.x, acc[0]);
        acc[1] = ffma2(w2, q0.y, acc[1]);
        acc[2] = ffma2(w2, q1.x, acc[2]);
        acc[3] = ffma2(w2, q1.y, acc[3]);
        acc[4] = ffma2(w2, q2.x, acc[4]);
        acc[5] = ffma2(w2, q2.y, acc[5]);
        acc[6] = ffma2(w2, q3.x, acc[6]);
        acc[7] = ffma2(w2, q3.y, acc[7]);
    }

    // max over all 16 rotations
    float mx = -1e30f;
#pragma unroll
    for (int j = 0; j < 8; j++) {
        float2 q = unpack2(acc[j]);
        mx = fmaxf(mx, fmaxf(q.x, q.y));
    }
    d_DESC[(size_t)s * 400 + f * 80 + gp] =
        fmaxf(mx + bc[f * 80 + gp], 0.0f);
}

// ---------------------------------------------------------------------------
// k4: grid 64, block 320 = (s_local 0..3, g 0..79). fw staged via smem chunks.
// Desc rows are final (max+bias+relu already applied by k3).
// ---------------------------------------------------------------------------
__global__ __launch_bounds__(320) void k4_fcc(const float* __restrict__ fw,
                                              const float* __restrict__ fb,
                                              float* __restrict__ out)
{
    __shared__ float fwsh[100 * 80];   // 32 KB chunk
    __shared__ float dsh[4 * 400];

    int tid = threadIdx.x;
    int sl  = tid / 80;
    int g   = tid % 80;
    int sb  = blockIdx.x * 4;

    {
        const float4* src = (const float4*)(d_DESC + (size_t)sb * 400);
        float4* dst = (float4*)dsh;
        for (int i = tid; i < 400; i += 320) dst[i] = src[i];
    }

    float acc = 0.0f;
#pragma unroll
    for (int c = 0; c < 4; c++) {
        __syncthreads();
        const float4* src = (const float4*)(fw + (size_t)c * 100 * 80);
        float4* dst = (float4*)fwsh;
        for (int i = tid; i < 2000; i += 320) dst[i] = src[i];
        __syncthreads();

        const float* dr = &dsh[sl * 400 + c * 100];
#pragma unroll 5
        for (int j = 0; j < 100; j++)
            acc = fmaf(dr[j], fwsh[j * 80 + g], acc);
    }

    out[(size_t)(sb + sl) * 80 + g] = fb[g] + acc;
}

// ---------------------------------------------------------------------------
// k5: distances + score + loss. 1024 threads; warp-per-pair, float4 loads,
// shfl reductions. out: [0:20480) desc, [20480] loss, [20481:20609) score
// ---------------------------------------------------------------------------
__global__ __launch_bounds__(1024) void k5_loss(float* __restrict__ out)
{
    __shared__ float sdist[128];
    __shared__ float stats[4];

    int tid  = threadIdx.x;
    int w    = tid >> 5;
    int lane = tid & 31;
    const float* gd = out;

#pragma unroll
    for (int i = 0; i < 4; i++) {
        int p  = w + 32 * i;     // 0..127
        int il = p & 63;
        const float *xa, *xb;
        if (p < 64) { xa = gd + (size_t)(64 + il) * 80;  xb = gd + (size_t)il * 80; }
        else        { xa = gd + (size_t)(128 + il) * 80; xb = gd + (size_t)(192 + il) * 80; }
        float sum = 0.0f;
        if (lane < 20) {
            float4 a4 = ((const float4*)xa)[lane];
            float4 b4 = ((const float4*)xb)[lane];
            float dx = a4.x - b4.x, dy = a4.y - b4.y;
            float dz = a4.z - b4.z, dw = a4.w - b4.w;
            sum = dx * dx + dy * dy + dz * dz + dw * dw;
        }
#pragma unroll
        for (int off = 16; off; off >>= 1)
            sum += __shfl_xor_sync(0xffffffffu, sum, off);
        if (lane == 0) { sdist[p] = sum; out[20481 + p] = sum; }
    }
    __syncthreads();

    if (w == 0) {
        float v1 = fmaxf(sdist[lane], 0.0f);
        float v2 = fmaxf(sdist[lane + 32], 0.0f);
        float sum = v1 + v2;
#pragma unroll
        for (int off = 16; off; off >>= 1)
            sum += __shfl_xor_sync(0xffffffffu, sum, off);
        float m = sum * (1.0f / 64.0f);
        float q = (v1 - m) * (v1 - m) + (v2 - m) * (v2 - m);
#pragma unroll
        for (int off = 16; off; off >>= 1)
            q += __shfl_xor_sync(0xffffffffu, q, off);
        if (lane == 0) { stats[0] = m; stats[1] = q; }
    } else if (w == 1) {
        float v1 = fmaxf(10.0f - sdist[64 + lane], 0.0f);
        float v2 = fmaxf(10.0f - sdist[96 + lane], 0.0f);
        float sum = v1 + v2;
#pragma unroll
        for (int off = 16; off; off >>= 1)
            sum += __shfl_xor_sync(0xffffffffu, sum, off);
        float m = sum * (1.0f / 64.0f);
        float q = (v1 - m) * (v1 - m) + (v2 - m) * (v2 - m);
#pragma unroll
        for (int off = 16; off; off >>= 1)
            q += __shfl_xor_sync(0xffffffffu, q, off);
        if (lane == 0) { stats[2] = m; stats[3] = q; }
    }
    __syncthreads();

    if (tid == 0)
        out[20480] = sqrtf(stats[1] / 63.0f) + sqrtf(stats[3] / 63.0f)
                   + stats[0] + stats[2];
}

// ---------------------------------------------------------------------------
extern "C" void kernel_launch(void* const* d_in, const int* in_sizes, int n_in,
                              void* d_out, int out_size)
{
    const float* input_feat  = (const float*)d_in[0];
    const float* rho_coords  = (const float*)d_in[1];
    const float* theta_coord = (const float*)d_in[2];
    const float* mask        = (const float*)d_in[3];
    const float* mu_rho      = (const float*)d_in[4];
    const float* sigma_rho   = (const float*)d_in[5];
    const float* mu_theta    = (const float*)d_in[6];
    const float* sigma_theta = (const float*)d_in[7];
    const float* W_conv      = (const float*)d_in[8];
    const float* b_conv      = (const float*)d_in[9];
    const float* fcc_w       = (const float*)d_in[10];
    const float* fcc_b       = (const float*)d_in[11];
    float* out = (float*)d_out;

    k12<<<S_N, 256>>>(input_feat, rho_coords, theta_coord, mask,
                      mu_rho, sigma_rho, mu_theta, sigma_theta);
    k3_conv<<<S_N, 400>>>(W_conv, b_conv);
    k4_fcc<<<S_N / 4, 320>>>(fcc_w, fcc_b, out);
    k5_loss<<<1, 1024>>>(out);
}

// round 13
// speedup vs baseline: 1.1113x; 1.0309x over previous
#include <cuda_runtime.h>
#include <math.h>

// Problem constants
#define S_N   256
#define V_N   200
#define F_N   5
#define G_N   80
#define NT    16
#define NR    5
#define NROT  16
#define EPSF  1e-5f

#define TWO_PI_F 6.28318530717958647692f
#define DTH_F    0.39269908169872415481f
#define LOG2E_F  1.44269504088896340736f

typedef unsigned long long ull;

// Scratch
__device__ float d_DESC[(size_t)S_N * 400];    // [s][f*80+gp], post max+bias+relu

// ---------------- packed f32x2 helpers ----------------
__device__ __forceinline__ ull ffma2(ull a, ull b, ull c) {
    ull d;
    asm("fma.rn.f32x2 %0, %1, %2, %3;" : "=l"(d) : "l"(a), "l"(b), "l"(c));
    return d;
}
__device__ __forceinline__ ull addf2(ull a, ull b) {
    ull d;
    asm("add.rn.f32x2 %0, %1, %2;" : "=l"(d) : "l"(a), "l"(b));
    return d;
}
__device__ __forceinline__ ull pack2(float x) {
    ull d;
    asm("mov.b64 %0, {%1, %1};" : "=l"(d) : "f"(x));
    return d;
}
__device__ __forceinline__ ull pack2f(float a, float b) {
    ull d;
    asm("mov.b64 %0, {%1, %2};" : "=l"(d) : "f"(a), "f"(b));
    return d;
}
__device__ __forceinline__ float2 unpack2(ull v) {
    float2 f;
    asm("mov.b64 {%0, %1}, %2;" : "=f"(f.x), "=f"(f.y) : "l"(v));
    return f;
}
__device__ __forceinline__ float ex2f(float x) {
    float r;
    asm("ex2.approx.f32 %0, %1;" : "=f"(r) : "f"(x));
    return r;
}

// ---------------------------------------------------------------------------
// k123 (fused gaussian-GEMM + conv + max + bias + relu): one block per s,
// 256 threads = (v-half 0/1) x (r2 0..7, k 0..15).
// Phase 1: 2-rotation FFMA2 GEMM over the half's 100 v (R9/R12 proven loop).
// Phase 2: combine halves via smem, normalize, write GDN to SMEM (not global)
//          in [g][f][rp][2] layout.
// Phase 3: conv GEMM vs W (pre-staged in Wsh during phase 0), max over the
//          16 rotations, bias + relu -> d_DESC.
// ---------------------------------------------------------------------------
__global__ __launch_bounds__(256, 2)
void k123(const float* __restrict__ feat,
          const float* __restrict__ rho,
          const float* __restrict__ theta,
          const float* __restrict__ mask,
          const float* __restrict__ mu_rho,
          const float* __restrict__ sigma_rho,
          const float* __restrict__ mu_theta,
          const float* __restrict__ sigma_theta,
          const float* __restrict__ Wc,
          const float* __restrict__ bc)
{
    __shared__ float As[(V_N + 2) * 32];   // 25.9 KB; later reused: cbuf / gdn
    __shared__ float t_s[V_N];
    __shared__ float Wsh[G_N * G_N];       // 25.6 KB

    int s   = blockIdx.x;
    int tid = threadIdx.x;
    int vh  = tid >> 7;                    // v half
    int l   = tid & 127;
    int r2  = l >> 4;                      // 0..7
    int k   = l & 15;

    // theta-gaussian constants (one k, two rotations)
    float mu_k  = __ldg(&mu_theta[k]);
    float st    = __ldg(&sigma_theta[k]);
    float sL    = sqrtf(LOG2E_F / (st * st + EPSF));
    float rdelA = (float)r2 * DTH_F;
    float rdelB = (float)(r2 + 8) * DTH_F;
    float c0    = -mu_k * sL;
    float c1    = -(TWO_PI_F + mu_k) * sL;

    // ---- stage W (all threads) ----
    {
        const float4* wsrc = (const float4*)Wc;
        float4* wdst = (float4*)Wsh;
        for (int i = tid; i < 1600; i += 256) wdst[i] = wsrc[i];
    }

    // ---- stage A, all 200 rows (float4 stores) ----
    if (tid < V_N) {
        int v   = tid;
        int idx = s * V_N + v;
        float rhv = rho[idx];
        float m   = mask[idx];
        t_s[v]    = theta[idx];
        float fv[5];
#pragma unroll
        for (int f = 0; f < 5; f++) fv[f] = feat[idx * 5 + f];
        float ar[32];
#pragma unroll
        for (int p = 0; p < NR; p++) {
            float mr = __ldg(&mu_rho[p * 16]);
            float sr = __ldg(&sigma_rho[p * 16]);
            float d  = rhv - mr;
            float rg = ex2f(-(d * d) * (LOG2E_F / (sr * sr + EPSF)));
            float rm = rg * m;
            ar[p * 6] = rm;
#pragma unroll
            for (int f = 0; f < 5; f++) ar[p * 6 + 1 + f] = rm * fv[f];
        }
        ar[30] = 0.0f; ar[31] = 0.0f;
        float4* dst = (float4*)(As + v * 32);
#pragma unroll
        for (int j4 = 0; j4 < 8; j4++) dst[j4] = ((const float4*)ar)[j4];
    } else if (tid < V_N + 16) {
        ((float4*)(As + V_N * 32))[tid - V_N] = make_float4(0.f, 0.f, 0.f, 0.f);
    }
    __syncthreads();

    // ---- phase 1: 100 v of this half, 2 rotations per thread ----
    ull accA[16], accB[16];
#pragma unroll
    for (int j = 0; j < 16; j++) { accA[j] = 0ull; accB[j] = 0ull; }

    const int vbase = vh * 100;
    ulonglong2 qA[4], qB[4];
    {
        const ulonglong2* row0 = (const ulonglong2*)(As + vbase * 32);
#pragma unroll
        for (int j = 0; j < 4; j++) qA[j] = row0[j];
    }

#pragma unroll 2
    for (int vo = 0; vo < 100; vo += 2) {
        int v = vbase + vo;
        // --- even: consume qA, prefetch row v+1 into qB ---
        {
            const ulonglong2* rn = (const ulonglong2*)(As + (v + 1) * 32);
#pragma unroll
            for (int j = 0; j < 4; j++) qB[j] = rn[j];
        }
        {
            float tv  = t_s[v];
            float trA = tv + rdelA;
            float cA  = (trA >= TWO_PI_F) ? c1 : c0;
            float xA  = fmaf(trA, sL, cA);
            ull tgA   = pack2(ex2f(-xA * xA));
            float trB = tv + rdelB;
            float cB  = (trB >= TWO_PI_F) ? c1 : c0;
            float xB  = fmaf(trB, sL, cB);
            ull tgB   = pack2(ex2f(-xB * xB));
#pragma unroll
            for (int j = 0; j < 4; j++) {
                accA[2 * j + 0] = ffma2(tgA, qA[j].x, accA[2 * j + 0]);
                accA[2 * j + 1] = ffma2(tgA, qA[j].y, accA[2 * j + 1]);
                accB[2 * j + 0] = ffma2(tgB, qA[j].x, accB[2 * j + 0]);
                accB[2 * j + 1] = ffma2(tgB, qA[j].y, accB[2 * j + 1]);
            }
            const ulonglong2* rv = (const ulonglong2*)(As + v * 32) + 4;
#pragma unroll
            for (int j = 0; j < 4; j++) {
                ulonglong2 q = rv[j];
                accA[8 + 2 * j + 0] = ffma2(tgA, q.x, accA[8 + 2 * j + 0]);
                accA[8 + 2 * j + 1] = ffma2(tgA, q.y, accA[8 + 2 * j + 1]);
                accB[8 + 2 * j + 0] = ffma2(tgB, q.x, accB[8 + 2 * j + 0]);
                accB[8 + 2 * j + 1] = ffma2(tgB, q.y, accB[8 + 2 * j + 1]);
            }
        }
        // --- odd: consume qB, prefetch row v+2 into qA ---
        {
            const ulonglong2* rn = (const ulonglong2*)(As + (v + 2) * 32);
#pragma unroll
            for (int j = 0; j < 4; j++) qA[j] = rn[j];
        }
        {
            float tv  = t_s[v + 1];
            float trA = tv + rdelA;
            float cA  = (trA >= TWO_PI_F) ? c1 : c0;
            float xA  = fmaf(trA, sL, cA);
            ull tgA   = pack2(ex2f(-xA * xA));
            float trB = tv + rdelB;
            float cB  = (trB >= TWO_PI_F) ? c1 : c0;
            float xB  = fmaf(trB, sL, cB);
            ull tgB   = pack2(ex2f(-xB * xB));
#pragma unroll
            for (int j = 0; j < 4; j++) {
                accA[2 * j + 0] = ffma2(tgA, qB[j].x, accA[2 * j + 0]);
                accA[2 * j + 1] = ffma2(tgA, qB[j].y, accA[2 * j + 1]);
                accB[2 * j + 0] = ffma2(tgB, qB[j].x, accB[2 * j + 0]);
                accB[2 * j + 1] = ffma2(tgB, qB[j].y, accB[2 * j + 1]);
            }
            const ulonglong2* rv = (const ulonglong2*)(As + (v + 1) * 32) + 4;
#pragma unroll
            for (int j = 0; j < 4; j++) {
                ulonglong2 q = rv[j];
                accA[8 + 2 * j + 0] = ffma2(tgA, q.x, accA[8 + 2 * j + 0]);
                accA[8 + 2 * j + 1] = ffma2(tgA, q.y, accA[8 + 2 * j + 1]);
                accB[8 + 2 * j + 0] = ffma2(tgB, q.x, accB[8 + 2 * j + 0]);
                accB[8 + 2 * j + 1] = ffma2(tgB, q.y, accB[8 + 2 * j + 1]);
            }
        }
    }

    // ---- phase 2: combine halves via smem (cbuf in As region) ----
    ull* cbuf = (ull*)As;   // 16 * 128 ull = 16 KB
    __syncthreads();        // done reading As/t_s
    if (vh == 1) {
#pragma unroll
        for (int j = 0; j < 16; j++) cbuf[j * 128 + l] = accA[j];
    }
    __syncthreads();
    if (vh == 0) {
#pragma unroll
        for (int j = 0; j < 16; j++) accA[j] = addf2(accA[j], cbuf[j * 128 + l]);
    }
    __syncthreads();
    if (vh == 1) {
#pragma unroll
        for (int j = 0; j < 16; j++) cbuf[j * 128 + l] = accB[j];
    }
    __syncthreads();
    if (vh == 0) {
#pragma unroll
        for (int j = 0; j < 16; j++) accB[j] = addf2(accB[j], cbuf[j * 128 + l]);
    }
    __syncthreads();   // all cbuf reads done before gdn overwrites the region

    // ---- normalize + write GDN to SMEM [g][f][rp][2] (vh0 threads) ----
    ull* gdn = (ull*)As;   // 3200 ull = 25.6 KB (fits As)
    if (vh == 0) {
#pragma unroll
        for (int p = 0; p < NR; p++) {
            float2 a0 = unpack2(accA[p * 3 + 0]);
            float2 a1 = unpack2(accA[p * 3 + 1]);
            float2 a2 = unpack2(accA[p * 3 + 2]);
            float2 b0 = unpack2(accB[p * 3 + 0]);
            float2 b1 = unpack2(accB[p * 3 + 1]);
            float2 b2 = unpack2(accB[p * 3 + 2]);
            float invA = 1.0f / (a0.x + EPSF);
            float invB = 1.0f / (b0.x + EPSF);
            int g = p * 16 + k;
            ull* gb = gdn + ((size_t)g * 5) * 8 + r2;
            gb[0 * 8] = pack2f(a0.y * invA, b0.y * invB);   // f0
            gb[1 * 8] = pack2f(a1.x * invA, b1.x * invB);   // f1
            gb[2 * 8] = pack2f(a1.y * invA, b1.y * invB);   // f2
            gb[3 * 8] = pack2f(a2.x * invA, b2.x * invB);   // f3
            gb[4 * 8] = pack2f(a2.y * invA, b2.y * invB);   // f4
        }
    }
    __syncthreads();

    // ---- phase 3: conv + max + bias + relu. 256 threads cover 400 cells:
    // cell0 = tid, cell1 = tid + 256 (if tid < 144).
    {
        int f0 = tid / 80, gp0 = tid % 80;
        int c1i = tid + 256;
        int f1 = c1i / 80, gp1 = c1i % 80;
        bool has1 = (tid < 144);

        ull acc0[8], acc1[8];
#pragma unroll
        for (int j = 0; j < 8; j++) { acc0[j] = 0ull; acc1[j] = 0ull; }

#pragma unroll 4
        for (int g = 0; g < G_N; g++) {
            ull w0 = pack2(Wsh[g * 80 + gp0]);
            const ulonglong2* rp0 = (const ulonglong2*)(gdn + ((size_t)g * 5 + f0) * 8);
            ulonglong2 q0 = rp0[0], q1 = rp0[1], q2 = rp0[2], q3 = rp0[3];
            acc0[0] = ffma2(w0, q0.x, acc0[0]);
            acc0[1] = ffma2(w0, q0.y, acc0[1]);
            acc0[2] = ffma2(w0, q1.x, acc0[2]);
            acc0[3] = ffma2(w0, q1.y, acc0[3]);
            acc0[4] = ffma2(w0, q2.x, acc0[4]);
            acc0[5] = ffma2(w0, q2.y, acc0[5]);
            acc0[6] = ffma2(w0, q3.x, acc0[6]);
            acc0[7] = ffma2(w0, q3.y, acc0[7]);
            if (has1) {
                ull w1 = pack2(Wsh[g * 80 + gp1]);
                const ulonglong2* rp1 = (const ulonglong2*)(gdn + ((size_t)g * 5 + f1) * 8);
                ulonglong2 p0 = rp1[0], p1 = rp1[1], p2 = rp1[2], p3 = rp1[3];
                acc1[0] = ffma2(w1, p0.x, acc1[0]);
                acc1[1] = ffma2(w1, p0.y, acc1[1]);
                acc1[2] = ffma2(w1, p1.x, acc1[2]);
                acc1[3] = ffma2(w1, p1.y, acc1[3]);
                acc1[4] = ffma2(w1, p2.x, acc1[4]);
                acc1[5] = ffma2(w1, p2.y, acc1[5]);
                acc1[6] = ffma2(w1, p3.x, acc1[6]);
                acc1[7] = ffma2(w1, p3.y, acc1[7]);
            }
        }

        float mx0 = -1e30f;
#pragma unroll
        for (int j = 0; j < 8; j++) {
            float2 q = unpack2(acc0[j]);
            mx0 = fmaxf(mx0, fmaxf(q.x, q.y));
        }
        d_DESC[(size_t)s * 400 + tid] = fmaxf(mx0 + bc[tid], 0.0f);

        if (has1) {
            float mx1 = -1e30f;
#pragma unroll
            for (int j = 0; j < 8; j++) {
                float2 q = unpack2(acc1[j]);
                mx1 = fmaxf(mx1, fmaxf(q.x, q.y));
            }
            d_DESC[(size_t)s * 400 + c1i] = fmaxf(mx1 + bc[c1i], 0.0f);
        }
    }
}

// ---------------------------------------------------------------------------
// k4: grid 64, block 320 = (s_local 0..3, g 0..79). fw staged via smem chunks.
// ---------------------------------------------------------------------------
__global__ __launch_bounds__(320) void k4_fcc(const float* __restrict__ fw,
                                              const float* __restrict__ fb,
                                              float* __restrict__ out)
{
    __shared__ float fwsh[100 * 80];   // 32 KB chunk
    __shared__ float dsh[4 * 400];

    int tid = threadIdx.x;
    int sl  = tid / 80;
    int g   = tid % 80;
    int sb  = blockIdx.x * 4;

    {
        const float4* src = (const float4*)(d_DESC + (size_t)sb * 400);
        float4* dst = (float4*)dsh;
        for (int i = tid; i < 400; i += 320) dst[i] = src[i];
    }

    float acc = 0.0f;
#pragma unroll
    for (int c = 0; c < 4; c++) {
        __syncthreads();
        const float4* src = (const float4*)(fw + (size_t)c * 100 * 80);
        float4* dst = (float4*)fwsh;
        for (int i = tid; i < 2000; i += 320) dst[i] = src[i];
        __syncthreads();

        const float* dr = &dsh[sl * 400 + c * 100];
#pragma unroll 5
        for (int j = 0; j < 100; j++)
            acc = fmaf(dr[j], fwsh[j * 80 + g], acc);
    }

    out[(size_t)(sb + sl) * 80 + g] = fb[g] + acc;
}

// ---------------------------------------------------------------------------
// k5: distances + score + loss. 1024 threads; warp-per-pair, float4 loads,
// shfl reductions. out: [0:20480) desc, [20480] loss, [20481:20609) score
// ---------------------------------------------------------------------------
__global__ __launch_bounds__(1024) void k5_loss(float* __restrict__ out)
{
    __shared__ float sdist[128];
    __shared__ float stats[4];

    int tid  = threadIdx.x;
    int w    = tid >> 5;
    int lane = tid & 31;
    const float* gd = out;

#pragma unroll
    for (int i = 0; i < 4; i++) {
        int p  = w + 32 * i;     // 0..127
        int il = p & 63;
        const float *xa, *xb;
        if (p < 64) { xa = gd + (size_t)(64 + il) * 80;  xb = gd + (size_t)il * 80; }
        else        { xa = gd + (size_t)(128 + il) * 80; xb = gd + (size_t)(192 + il) * 80; }
        float sum = 0.0f;
        if (lane < 20) {
            float4 a4 = ((const float4*)xa)[lane];
            float4 b4 = ((const float4*)xb)[lane];
            float dx = a4.x - b4.x, dy = a4.y - b4.y;
            float dz = a4.z - b4.z, dw = a4.w - b4.w;
            sum = dx * dx + dy * dy + dz * dz + dw * dw;
        }
#pragma unroll
        for (int off = 16; off; off >>= 1)
            sum += __shfl_xor_sync(0xffffffffu, sum, off);
        if (lane == 0) { sdist[p] = sum; out[20481 + p] = sum; }
    }
    __syncthreads();

    if (w == 0) {
        float v1 = fmaxf(sdist[lane], 0.0f);
        float v2 = fmaxf(sdist[lane + 32], 0.0f);
        float sum = v1 + v2;
#pragma unroll
        for (int off = 16; off; off >>= 1)
            sum += __shfl_xor_sync(0xffffffffu, sum, off);
        float m = sum * (1.0f / 64.0f);
        float q = (v1 - m) * (v1 - m) + (v2 - m) * (v2 - m);
#pragma unroll
        for (int off = 16; off; off >>= 1)
            q += __shfl_xor_sync(0xffffffffu, q, off);
        if (lane == 0) { stats[0] = m; stats[1] = q; }
    } else if (w == 1) {
        float v1 = fmaxf(10.0f - sdist[64 + lane], 0.0f);
        float v2 = fmaxf(10.0f - sdist[96 + lane], 0.0f);
        float sum = v1 + v2;
#pragma unroll
        for (int off = 16; off; off >>= 1)
            sum += __shfl_xor_sync(0xffffffffu, sum, off);
        float m = sum * (1.0f / 64.0f);
        float q = (v1 - m) * (v1 - m) + (v2 - m) * (v2 - m);
#pragma unroll
        for (int off = 16; off; off >>= 1)
            q += __shfl_xor_sync(0xffffffffu, q, off);
        if (lane == 0) { stats[2] = m; stats[3] = q; }
    }
    __syncthreads();

    if (tid == 0)
        out[20480] = sqrtf(stats[1] / 63.0f) + sqrtf(stats[3] / 63.0f)
                   + stats[0] + stats[2];
}

// ---------------------------------------------------------------------------
extern "C" void kernel_launch(void* const* d_in, const int* in_sizes, int n_in,
                              void* d_out, int out_size)
{
    const float* input_feat  = (const float*)d_in[0];
    const float* rho_coords  = (const float*)d_in[1];
    const float* theta_coord = (const float*)d_in[2];
    const float* mask        = (const float*)d_in[3];
    const float* mu_rho      = (const float*)d_in[4];
    const float* sigma_rho   = (const float*)d_in[5];
    const float* mu_theta    = (const float*)d_in[6];
    const float* sigma_theta = (const float*)d_in[7];
    const float* W_conv      = (const float*)d_in[8];
    const float* b_conv      = (const float*)d_in[9];
    const float* fcc_w       = (const float*)d_in[10];
    const float* fcc_b       = (const float*)d_in[11];
    float* out = (float*)d_out;

    k123<<<S_N, 256>>>(input_feat, rho_coords, theta_coord, mask,
                       mu_rho, sigma_rho, mu_theta, sigma_theta,
                       W_conv, b_conv);
    k4_fcc<<<S_N / 4, 320>>>(fcc_w, fcc_b, out);
    k5_loss<<<1, 1024>>>(out);
}